// round 9
// baseline (speedup 1.0000x reference)
#include <cuda_runtime.h>
#include <cuda_fp16.h>

// APRConv1x1, two K=32 HMMA GEMMs + select (R5/R6/R8 proven core).
// R9 delta (R8 ncu: 128 of ~313 L1 cyc/tile were STG wavefronts — each
// fragment STG.64 touches 8 output rows = 8 lines):
//   transpose epilogue through warp-private smem (pitch-76 perfect bank
//   permutation) -> 8 dense STG.128 (4 lines each): store wf 128 -> 32.
// Engine (loads, staging, ldmatrix, MMA, select) unchanged from R8.

#define THREADS 128
#define OPITCH 76u          // words; (12r+2t) mod 32 distinct over 32 lanes

__global__ __launch_bounds__(THREADS, 6)
void apr_mma6_kernel(const float* __restrict__ x,
                     const float* __restrict__ Wg,    // [16][16][4]
                     const float* __restrict__ bias,  // [16]
                     const int*   __restrict__ sidx,  // [P]
                     float* __restrict__ out,         // [B][16][N]
                     unsigned Nn, unsigned P)
{
    __shared__ __align__(16) char  stage[4][4096];        // 32 rows x 128B per warp
    __shared__ __align__(16) float obuf[4][16 * OPITCH];  // transpose buffer per warp

    const int tid = threadIdx.x;
    const int wid = tid >> 5;
    const int l   = tid & 31;
    const int t   = l & 3;
    const int r   = l >> 2;

    // ---- once: weight A-fragments (k = 2i + j; W_h[o][2i+j] = Wg[o*64+4i+2h+j]) ----
    unsigned a[2][2][4];
#pragma unroll
    for (int h = 0; h < 2; h++)
#pragma unroll
        for (int ks = 0; ks < 2; ks++) {
            const int i0 = 8 * ks + t;
            const int i1 = 8 * ks + 4 + t;
            float2 w; __half2 hh;
            w = *(const float2*)(Wg + r * 64 + i0 * 4 + 2 * h);
            hh = __floats2half2_rn(w.x, w.y); a[h][ks][0] = *(unsigned*)&hh;
            w = *(const float2*)(Wg + (r + 8) * 64 + i0 * 4 + 2 * h);
            hh = __floats2half2_rn(w.x, w.y); a[h][ks][1] = *(unsigned*)&hh;
            w = *(const float2*)(Wg + r * 64 + i1 * 4 + 2 * h);
            hh = __floats2half2_rn(w.x, w.y); a[h][ks][2] = *(unsigned*)&hh;
            w = *(const float2*)(Wg + (r + 8) * 64 + i1 * 4 + 2 * h);
            hh = __floats2half2_rn(w.x, w.y); a[h][ks][3] = *(unsigned*)&hh;
        }
    const float br0 = __ldg(bias + r);
    const float br8 = __ldg(bias + r + 8);

    const unsigned wtiles = (P + 63) >> 6;
    const unsigned wstep  = (unsigned)gridDim.x * 4;
    unsigned wt = (unsigned)blockIdx.x * 4 + wid;
    if (wt >= wtiles) return;

    const unsigned sbase = (unsigned)__cvta_generic_to_shared(stage[wid]);
    const unsigned obase = (unsigned)__cvta_generic_to_shared(obuf[wid]);

    // write-side lane constants (lane owns row l = points 2l, 2l+1)
    const unsigned permw = (((unsigned)l & 3u) << 1) | (((unsigned)l >> 2) & 1u);
    const unsigned waddr = sbase + ((unsigned)l << 7);
    // read-side lane constants (ldmatrix)
    const unsigned wrd   = ((unsigned)l & 7u) >> 1;
    const unsigned bsx   = ((((unsigned)l >> 3) << 1) + ((unsigned)l & 1u)) ^ (wrd << 1);
    const unsigned raddr0 = sbase + (wrd << 7);
    // epilogue transpose constants
    const unsigned oa0 = obase + ((unsigned)r * OPITCH + 2u * (unsigned)t) * 4u;          // + 8g*4
    const unsigned oa8 = obase + (((unsigned)r + 8u) * OPITCH + 2u * (unsigned)t) * 4u;
    const unsigned chA = ((unsigned)l >> 4);        // 0/1: channel parity within pair
    const unsigned ptw = ((unsigned)l & 15u) * 4u;  // 4 consecutive points per lane

    // ---- prologue: load tile wt (points 2l, 2l+1 for 16 channels) ----
    float2 fv[16]; int2 sv;
    {
        unsigned wtb = wt << 6; if (wtb + 64u > P) wtb = P - 64u;
        const unsigned b  = wtb >= Nn ? 1u : 0u;
        const unsigned n0 = wtb - b * Nn;
        const float* xp = x + (size_t)b * 16u * Nn + n0 + 2u * (unsigned)l;
#pragma unroll
        for (int i = 0; i < 16; i++)
            fv[i] = *reinterpret_cast<const float2*>(xp + (size_t)((unsigned)i * Nn));
        sv = *reinterpret_cast<const int2*>(sidx + wtb + 2u * (unsigned)l);
    }

    for (;;) {
        unsigned wtb = wt << 6; if (wtb + 64u > P) wtb = P - 64u;
        const unsigned b  = wtb >= Nn ? 1u : 0u;
        const unsigned n0 = wtb - b * Nn;
        float* fo = out + (size_t)b * 16u * Nn + n0;

        const int s_e = sv.x, s_o = sv.y;
        const unsigned sh_e = ((unsigned)s_e & 1u) << 4;
        const unsigned sh_o = ((unsigned)s_o & 1u) << 4;

        // ---- pack + stage current tile (8x STS.128, conflict-free) ----
#pragma unroll
        for (int cc = 0; cc < 4; cc++) {
            unsigned e0, e1, e2, e3, o0, o1, o2, o3;
            e0 = (unsigned)__half_as_ushort(__float2half(fv[4*cc+0].x)) << sh_e;
            e1 = (unsigned)__half_as_ushort(__float2half(fv[4*cc+1].x)) << sh_e;
            e2 = (unsigned)__half_as_ushort(__float2half(fv[4*cc+2].x)) << sh_e;
            e3 = (unsigned)__half_as_ushort(__float2half(fv[4*cc+3].x)) << sh_e;
            o0 = (unsigned)__half_as_ushort(__float2half(fv[4*cc+0].y)) << sh_o;
            o1 = (unsigned)__half_as_ushort(__float2half(fv[4*cc+1].y)) << sh_o;
            o2 = (unsigned)__half_as_ushort(__float2half(fv[4*cc+2].y)) << sh_o;
            o3 = (unsigned)__half_as_ushort(__float2half(fv[4*cc+3].y)) << sh_o;
            const unsigned ae = waddr + ((((unsigned)(2*cc))     ^ permw) << 4);
            const unsigned ao = waddr + ((((unsigned)(2*cc + 1)) ^ permw) << 4);
            asm volatile("st.shared.v4.b32 [%0], {%1,%2,%3,%4};"
                         :: "r"(ae), "r"(e0), "r"(e1), "r"(e2), "r"(e3));
            asm volatile("st.shared.v4.b32 [%0], {%1,%2,%3,%4};"
                         :: "r"(ao), "r"(o0), "r"(o1), "r"(o2), "r"(o3));
        }

        // ---- prefetch next tile into the SAME registers (WAR after pack) ----
        const unsigned wtn = wt + wstep;
        const bool more = wtn < wtiles;
        if (more) {
            unsigned wtb2 = wtn << 6; if (wtb2 + 64u > P) wtb2 = P - 64u;
            const unsigned b2 = wtb2 >= Nn ? 1u : 0u;
            const unsigned n2 = wtb2 - b2 * Nn;
            const float* xp = x + (size_t)b2 * 16u * Nn + n2 + 2u * (unsigned)l;
#pragma unroll
            for (int i = 0; i < 16; i++)
                fv[i] = *reinterpret_cast<const float2*>(xp + (size_t)((unsigned)i * Nn));
            sv = *reinterpret_cast<const int2*>(sidx + wtb2 + 2u * (unsigned)l);
        }
        __syncwarp();

        // ---- compute: 8 groups of 8 points; selected results -> smem obuf ----
#pragma unroll
        for (int g = 0; g < 8; g++) {
            const unsigned addr = raddr0 + ((unsigned)g << 9)
                                + ((bsx ^ ((unsigned)g & 1u)) << 4);
            unsigned b0, b1, b2, b3;
            asm volatile("ldmatrix.sync.aligned.m8n8.x4.shared.b16 {%0,%1,%2,%3}, [%4];"
                         : "=r"(b0), "=r"(b1), "=r"(b2), "=r"(b3) : "r"(addr));

            float dl0 = br0, dl1 = br0, dl2 = br8, dl3 = br8;
            float dh0 = br0, dh1 = br0, dh2 = br8, dh3 = br8;

            asm volatile("mma.sync.aligned.m16n8k16.row.col.f32.f16.f16.f32 "
                "{%0,%1,%2,%3}, {%4,%5,%6,%7}, {%8,%9}, {%0,%1,%2,%3};"
                : "+f"(dl0), "+f"(dl1), "+f"(dl2), "+f"(dl3)
                : "r"(a[0][0][0]), "r"(a[0][0][1]), "r"(a[0][0][2]), "r"(a[0][0][3]),
                  "r"(b0), "r"(b1));
            asm volatile("mma.sync.aligned.m16n8k16.row.col.f32.f16.f16.f32 "
                "{%0,%1,%2,%3}, {%4,%5,%6,%7}, {%8,%9}, {%0,%1,%2,%3};"
                : "+f"(dl0), "+f"(dl1), "+f"(dl2), "+f"(dl3)
                : "r"(a[0][1][0]), "r"(a[0][1][1]), "r"(a[0][1][2]), "r"(a[0][1][3]),
                  "r"(b2), "r"(b3));
            asm volatile("mma.sync.aligned.m16n8k16.row.col.f32.f16.f16.f32 "
                "{%0,%1,%2,%3}, {%4,%5,%6,%7}, {%8,%9}, {%0,%1,%2,%3};"
                : "+f"(dh0), "+f"(dh1), "+f"(dh2), "+f"(dh3)
                : "r"(a[1][0][0]), "r"(a[1][0][1]), "r"(a[1][0][2]), "r"(a[1][0][3]),
                  "r"(b0), "r"(b1));
            asm volatile("mma.sync.aligned.m16n8k16.row.col.f32.f16.f16.f32 "
                "{%0,%1,%2,%3}, {%4,%5,%6,%7}, {%8,%9}, {%0,%1,%2,%3};"
                : "+f"(dh0), "+f"(dh1), "+f"(dh2), "+f"(dh3)
                : "r"(a[1][1][0]), "r"(a[1][1][1]), "r"(a[1][1][2]), "r"(a[1][1][3]),
                  "r"(b2), "r"(b3));

            // select: s of points (8g+2t, 8g+2t+1) lives in lane 4g+t
            const int src = 4 * g + t;
            const int ss0 = __shfl_sync(0xffffffffu, s_e, src);
            const int ss1 = __shfl_sync(0xffffffffu, s_o, src);
            const float q0 = (ss0 & 2) ? dh0 : dl0;
            const float q1 = (ss1 & 2) ? dh1 : dl1;
            const float q2 = (ss0 & 2) ? dh2 : dl2;
            const float q3 = (ss1 & 2) ? dh3 : dl3;

            // stash into transpose buffer (perfect bank permutation)
            asm volatile("st.shared.v2.f32 [%0], {%1,%2};"
                         :: "r"(oa0 + (unsigned)(32 * g)), "f"(q0), "f"(q1));
            asm volatile("st.shared.v2.f32 [%0], {%1,%2};"
                         :: "r"(oa8 + (unsigned)(32 * g)), "f"(q2), "f"(q3));
        }
        __syncwarp();

        // ---- dense stores: 8x (LDS.128 + STG.128), 2 channels per instr ----
#pragma unroll
        for (int j = 0; j < 8; j++) {
            const unsigned ch = 2u * (unsigned)j + chA;
            float v0, v1, v2, v3;
            asm volatile("ld.shared.v4.f32 {%0,%1,%2,%3}, [%4];"
                         : "=f"(v0), "=f"(v1), "=f"(v2), "=f"(v3)
                         : "r"(obase + (ch * OPITCH + ptw) * 4u));
            *reinterpret_cast<float4*>(fo + (size_t)ch * Nn + ptw) =
                make_float4(v0, v1, v2, v3);
        }
        __syncwarp();   // obuf reads & ldmatrix done before next iteration's STS

        if (!more) break;
        wt = wtn;
    }
}

extern "C" void kernel_launch(void* const* d_in, const int* in_sizes, int n_in,
                              void* d_out, int out_size)
{
    const float* x    = (const float*)d_in[0];   // [B, 16, N]
    const float* Wg   = (const float*)d_in[1];   // [16, 16, 4, 1, 1]
    const float* bias = (const float*)d_in[2];   // [16]
    const int*   sidx = (const int*)d_in[3];     // [B, N]

    float* out = (float*)d_out;

    const unsigned P  = (unsigned)in_sizes[3];   // B*N
    const unsigned Nn = P / 2;                   // B = 2

    const unsigned wtiles = (P + 63) / 64;
    unsigned blk = (wtiles + 3) / 4;
    if (blk > 888) blk = 888;                    // 6 CTAs x 148 SMs, persistent

    apr_mma6_kernel<<<blk, THREADS>>>(x, Wg, bias, sidx, out, Nn, P);
}

// round 10
// speedup vs baseline: 1.1986x; 1.1986x over previous
#include <cuda_runtime.h>
#include <cuda_fp16.h>

// APRConv1x1, two K=32 HMMA GEMMs + select (R5/R6/R8 proven core).
// R10 (R8 was latency-exposed: 430-cyc tile wall < 577-cyc DRAM latency):
//   128-point warp tiles -> 66 lines in flight/warp and ~870-cyc iteration
//   wall > DRAM latency => steady-state exposure ~= 0.
//   Lane l owns rows l and l+32 (same swizzle perm, +4096B); 16 ldmatrix
//   groups; pack/MMA/select/fragment-store identical per point to R8.

#define THREADS 128

__global__ __launch_bounds__(THREADS, 4)
void apr_mma7_kernel(const float* __restrict__ x,
                     const float* __restrict__ Wg,    // [16][16][4]
                     const float* __restrict__ bias,  // [16]
                     const int*   __restrict__ sidx,  // [P]
                     float* __restrict__ out,         // [B][16][N]
                     unsigned Nn, unsigned P)
{
    __shared__ __align__(16) char stage[4][8192];   // 64 rows x 128B per warp

    const int tid = threadIdx.x;
    const int wid = tid >> 5;
    const int l   = tid & 31;
    const int t   = l & 3;
    const int r   = l >> 2;

    // ---- once: weight A-fragments (k = 2i + j; W_h[o][2i+j] = Wg[o*64+4i+2h+j]) ----
    unsigned a[2][2][4];
#pragma unroll
    for (int h = 0; h < 2; h++)
#pragma unroll
        for (int ks = 0; ks < 2; ks++) {
            const int i0 = 8 * ks + t;
            const int i1 = 8 * ks + 4 + t;
            float2 w; __half2 hh;
            w = *(const float2*)(Wg + r * 64 + i0 * 4 + 2 * h);
            hh = __floats2half2_rn(w.x, w.y); a[h][ks][0] = *(unsigned*)&hh;
            w = *(const float2*)(Wg + (r + 8) * 64 + i0 * 4 + 2 * h);
            hh = __floats2half2_rn(w.x, w.y); a[h][ks][1] = *(unsigned*)&hh;
            w = *(const float2*)(Wg + r * 64 + i1 * 4 + 2 * h);
            hh = __floats2half2_rn(w.x, w.y); a[h][ks][2] = *(unsigned*)&hh;
            w = *(const float2*)(Wg + (r + 8) * 64 + i1 * 4 + 2 * h);
            hh = __floats2half2_rn(w.x, w.y); a[h][ks][3] = *(unsigned*)&hh;
        }
    const float br0 = __ldg(bias + r);
    const float br8 = __ldg(bias + r + 8);

    const unsigned wtiles = (P + 127) >> 7;
    const unsigned wstep  = (unsigned)gridDim.x * 4;
    unsigned wt = (unsigned)blockIdx.x * 4 + wid;
    if (wt >= wtiles) return;

    const unsigned sbase = (unsigned)__cvta_generic_to_shared(stage[wid]);

    // write-side: lane owns rows l (pts 2l,2l+1) and l+32 (pts 64+2l,64+2l+1)
    const unsigned permw  = (((unsigned)l & 3u) << 1) | (((unsigned)l >> 2) & 1u);
    const unsigned waddr0 = sbase + ((unsigned)l << 7);       // +4096 for row l+32
    // read-side (ldmatrix), verified slot algebra from R8
    const unsigned wrd    = ((unsigned)l & 7u) >> 1;
    const unsigned bsx    = ((((unsigned)l >> 3) << 1) + ((unsigned)l & 1u)) ^ (wrd << 1);
    const unsigned raddr0 = sbase + (wrd << 7);
    // store row offsets
    const unsigned ro  = (unsigned)r * Nn;
    const unsigned ro8 = (unsigned)(r + 8) * Nn;

    // ---- prologue: load tile wt ----
    float2 fv0[16], fv1[16]; int2 sv0, sv1;
    {
        unsigned wtb = wt << 7; if (wtb + 128u > P) wtb = P - 128u;
        const unsigned b  = wtb >= Nn ? 1u : 0u;
        const unsigned n0 = wtb - b * Nn;
        const float* xp = x + (size_t)b * 16u * Nn + n0 + 2u * (unsigned)l;
#pragma unroll
        for (int i = 0; i < 16; i++) {
            fv0[i] = *reinterpret_cast<const float2*>(xp + (size_t)((unsigned)i * Nn));
            fv1[i] = *reinterpret_cast<const float2*>(xp + (size_t)((unsigned)i * Nn) + 64u);
        }
        sv0 = *reinterpret_cast<const int2*>(sidx + wtb + 2u * (unsigned)l);
        sv1 = *reinterpret_cast<const int2*>(sidx + wtb + 64u + 2u * (unsigned)l);
    }

    for (;;) {
        unsigned wtb = wt << 7; if (wtb + 128u > P) wtb = P - 128u;
        const unsigned b  = wtb >= Nn ? 1u : 0u;
        const unsigned n0 = wtb - b * Nn;
        float* fo = out + (size_t)b * 16u * Nn + n0;

        // keep current tile's stencil bits (survive the prefetch overwrite)
        const int se0 = sv0.x, so0 = sv0.y, se1 = sv1.x, so1 = sv1.y;

        // ---- pack + stage both halves (16x STS.128, conflict-free) ----
        {
            const unsigned she = ((unsigned)se0 & 1u) << 4;
            const unsigned sho = ((unsigned)so0 & 1u) << 4;
#pragma unroll
            for (int cc = 0; cc < 4; cc++) {
                unsigned e0, e1, e2, e3, o0, o1, o2, o3;
                e0 = (unsigned)__half_as_ushort(__float2half(fv0[4*cc+0].x)) << she;
                e1 = (unsigned)__half_as_ushort(__float2half(fv0[4*cc+1].x)) << she;
                e2 = (unsigned)__half_as_ushort(__float2half(fv0[4*cc+2].x)) << she;
                e3 = (unsigned)__half_as_ushort(__float2half(fv0[4*cc+3].x)) << she;
                o0 = (unsigned)__half_as_ushort(__float2half(fv0[4*cc+0].y)) << sho;
                o1 = (unsigned)__half_as_ushort(__float2half(fv0[4*cc+1].y)) << sho;
                o2 = (unsigned)__half_as_ushort(__float2half(fv0[4*cc+2].y)) << sho;
                o3 = (unsigned)__half_as_ushort(__float2half(fv0[4*cc+3].y)) << sho;
                const unsigned ae = waddr0 + ((((unsigned)(2*cc))     ^ permw) << 4);
                const unsigned ao = waddr0 + ((((unsigned)(2*cc + 1)) ^ permw) << 4);
                asm volatile("st.shared.v4.b32 [%0], {%1,%2,%3,%4};"
                             :: "r"(ae), "r"(e0), "r"(e1), "r"(e2), "r"(e3));
                asm volatile("st.shared.v4.b32 [%0], {%1,%2,%3,%4};"
                             :: "r"(ao), "r"(o0), "r"(o1), "r"(o2), "r"(o3));
            }
        }
        {
            const unsigned she = ((unsigned)se1 & 1u) << 4;
            const unsigned sho = ((unsigned)so1 & 1u) << 4;
#pragma unroll
            for (int cc = 0; cc < 4; cc++) {
                unsigned e0, e1, e2, e3, o0, o1, o2, o3;
                e0 = (unsigned)__half_as_ushort(__float2half(fv1[4*cc+0].x)) << she;
                e1 = (unsigned)__half_as_ushort(__float2half(fv1[4*cc+1].x)) << she;
                e2 = (unsigned)__half_as_ushort(__float2half(fv1[4*cc+2].x)) << she;
                e3 = (unsigned)__half_as_ushort(__float2half(fv1[4*cc+3].x)) << she;
                o0 = (unsigned)__half_as_ushort(__float2half(fv1[4*cc+0].y)) << sho;
                o1 = (unsigned)__half_as_ushort(__float2half(fv1[4*cc+1].y)) << sho;
                o2 = (unsigned)__half_as_ushort(__float2half(fv1[4*cc+2].y)) << sho;
                o3 = (unsigned)__half_as_ushort(__float2half(fv1[4*cc+3].y)) << sho;
                const unsigned ae = waddr0 + 4096u + ((((unsigned)(2*cc))     ^ permw) << 4);
                const unsigned ao = waddr0 + 4096u + ((((unsigned)(2*cc + 1)) ^ permw) << 4);
                asm volatile("st.shared.v4.b32 [%0], {%1,%2,%3,%4};"
                             :: "r"(ae), "r"(e0), "r"(e1), "r"(e2), "r"(e3));
                asm volatile("st.shared.v4.b32 [%0], {%1,%2,%3,%4};"
                             :: "r"(ao), "r"(o0), "r"(o1), "r"(o2), "r"(o3));
            }
        }

        // ---- prefetch next tile into the SAME registers (WAR after pack) ----
        const unsigned wtn = wt + wstep;
        const bool more = wtn < wtiles;
        if (more) {
            unsigned wtb2 = wtn << 7; if (wtb2 + 128u > P) wtb2 = P - 128u;
            const unsigned b2 = wtb2 >= Nn ? 1u : 0u;
            const unsigned n2 = wtb2 - b2 * Nn;
            const float* xp = x + (size_t)b2 * 16u * Nn + n2 + 2u * (unsigned)l;
#pragma unroll
            for (int i = 0; i < 16; i++) {
                fv0[i] = *reinterpret_cast<const float2*>(xp + (size_t)((unsigned)i * Nn));
                fv1[i] = *reinterpret_cast<const float2*>(xp + (size_t)((unsigned)i * Nn) + 64u);
            }
            sv0 = *reinterpret_cast<const int2*>(sidx + wtb2 + 2u * (unsigned)l);
            sv1 = *reinterpret_cast<const int2*>(sidx + wtb2 + 64u + 2u * (unsigned)l);
        }
        __syncwarp();

        // ---- compute: 16 groups of 8 points ----
#pragma unroll
        for (int g = 0; g < 16; g++) {
            const unsigned addr = raddr0 + ((unsigned)g << 9)
                                + ((bsx ^ ((unsigned)g & 1u)) << 4);
            unsigned b0, b1, b2, b3;
            asm volatile("ldmatrix.sync.aligned.m8n8.x4.shared.b16 {%0,%1,%2,%3}, [%4];"
                         : "=r"(b0), "=r"(b1), "=r"(b2), "=r"(b3) : "r"(addr));

            float dl0 = br0, dl1 = br0, dl2 = br8, dl3 = br8;
            float dh0 = br0, dh1 = br0, dh2 = br8, dh3 = br8;

            asm volatile("mma.sync.aligned.m16n8k16.row.col.f32.f16.f16.f32 "
                "{%0,%1,%2,%3}, {%4,%5,%6,%7}, {%8,%9}, {%0,%1,%2,%3};"
                : "+f"(dl0), "+f"(dl1), "+f"(dl2), "+f"(dl3)
                : "r"(a[0][0][0]), "r"(a[0][0][1]), "r"(a[0][0][2]), "r"(a[0][0][3]),
                  "r"(b0), "r"(b1));
            asm volatile("mma.sync.aligned.m16n8k16.row.col.f32.f16.f16.f32 "
                "{%0,%1,%2,%3}, {%4,%5,%6,%7}, {%8,%9}, {%0,%1,%2,%3};"
                : "+f"(dl0), "+f"(dl1), "+f"(dl2), "+f"(dl3)
                : "r"(a[0][1][0]), "r"(a[0][1][1]), "r"(a[0][1][2]), "r"(a[0][1][3]),
                  "r"(b2), "r"(b3));
            asm volatile("mma.sync.aligned.m16n8k16.row.col.f32.f16.f16.f32 "
                "{%0,%1,%2,%3}, {%4,%5,%6,%7}, {%8,%9}, {%0,%1,%2,%3};"
                : "+f"(dh0), "+f"(dh1), "+f"(dh2), "+f"(dh3)
                : "r"(a[1][0][0]), "r"(a[1][0][1]), "r"(a[1][0][2]), "r"(a[1][0][3]),
                  "r"(b0), "r"(b1));
            asm volatile("mma.sync.aligned.m16n8k16.row.col.f32.f16.f16.f32 "
                "{%0,%1,%2,%3}, {%4,%5,%6,%7}, {%8,%9}, {%0,%1,%2,%3};"
                : "+f"(dh0), "+f"(dh1), "+f"(dh2), "+f"(dh3)
                : "r"(a[1][1][0]), "r"(a[1][1][1]), "r"(a[1][1][2]), "r"(a[1][1][3]),
                  "r"(b2), "r"(b3));

            // select: s of points (8g+2t, 8g+2t+1); owner lane 4g+t (half 0)
            // or 4(g-8)+t (half 1)
            int ss0, ss1;
            if (g < 8) {
                const int src = 4 * g + t;
                ss0 = __shfl_sync(0xffffffffu, se0, src);
                ss1 = __shfl_sync(0xffffffffu, so0, src);
            } else {
                const int src = 4 * (g - 8) + t;
                ss0 = __shfl_sync(0xffffffffu, se1, src);
                ss1 = __shfl_sync(0xffffffffu, so1, src);
            }
            const float q0 = (ss0 & 2) ? dh0 : dl0;
            const float q1 = (ss1 & 2) ? dh1 : dl1;
            const float q2 = (ss0 & 2) ? dh2 : dl2;
            const float q3 = (ss1 & 2) ? dh3 : dl3;

            const unsigned p0 = (unsigned)(8 * g + 2 * t);
            *reinterpret_cast<float2*>(fo + ro  + p0) = make_float2(q0, q1);
            *reinterpret_cast<float2*>(fo + ro8 + p0) = make_float2(q2, q3);
        }
        __syncwarp();   // ldmatrix reads done before next iteration's STS

        if (!more) break;
        wt = wtn;
    }
}

extern "C" void kernel_launch(void* const* d_in, const int* in_sizes, int n_in,
                              void* d_out, int out_size)
{
    const float* x    = (const float*)d_in[0];   // [B, 16, N]
    const float* Wg   = (const float*)d_in[1];   // [16, 16, 4, 1, 1]
    const float* bias = (const float*)d_in[2];   // [16]
    const int*   sidx = (const int*)d_in[3];     // [B, N]

    float* out = (float*)d_out;

    const unsigned P  = (unsigned)in_sizes[3];   // B*N
    const unsigned Nn = P / 2;                   // B = 2

    const unsigned wtiles = (P + 127) / 128;
    unsigned blk = (wtiles + 3) / 4;
    if (blk > 592) blk = 592;                    // 4 CTAs x 148 SMs, persistent

    apr_mma7_kernel<<<blk, THREADS>>>(x, Wg, bias, sidx, out, Nn, P);
}